// round 12
// baseline (speedup 1.0000x reference)
#include <cuda_runtime.h>
#include <cuda_fp16.h>

#define N_NODES   50000
#define N_EDGES   800000
#define NUM_GRAPHS 512
#define F1 128
#define F2 64
#define DMAX 64    // fixed adjacency stride; P(deg>=64) ~ 1e-19 per node
#define NBLK 196   // ceil(N_NODES/256)

// ---------------- scratch (device globals: allocation-free) ----------------
// INVARIANT at kernel_launch entry: g_degi == 0, g_pool == 0 (zero-init at
// load; gather64_pool re-zeroes g_degi, final_kernel re-zeroes g_pool).
__device__ int    g_degi[N_NODES];
__device__ int    g_adjf[(size_t)N_NODES * DMAX];// fixed-stride adjacency (src per dst)
__device__ int    g_start[NUM_GRAPHS + 1];       // first node index of graph g
__device__ float  g_dinv[N_NODES];
__device__ __half g_h1[(size_t)N_NODES * F1];    // x@W1 (fp16)
__device__ __half g_agg1[(size_t)N_NODES * F1];  // relu(gcn1) (fp16)
__device__ __half g_hs2[(size_t)N_NODES * F2];   // dinv * (relu(agg1)@W2) (fp16)
__device__ float  g_pool[NUM_GRAPHS * F2];

// ---------------- static side stream + events ----------------
static cudaStream_t s_side;
static cudaEvent_t  s_ev_fork, s_ev_h1;
namespace {
struct StreamInit {
    StreamInit() {
        cudaStreamCreateWithFlags(&s_side, cudaStreamNonBlocking);
        cudaEventCreateWithFlags(&s_ev_fork, cudaEventDisableTiming);
        cudaEventCreateWithFlags(&s_ev_h1,   cudaEventDisableTiming);
    }
};
static StreamInit s_stream_init;
}

// ---------------- helpers ----------------
__device__ __forceinline__ float4 h4_to_f4(uint2 w) {
    __half2 lo = *reinterpret_cast<__half2*>(&w.x);
    __half2 hi = *reinterpret_cast<__half2*>(&w.y);
    float2 a = __half22float2(lo);
    float2 b = __half22float2(hi);
    return make_float4(a.x, a.y, b.x, b.y);
}
__device__ __forceinline__ unsigned h2bits(__half2 h) {
    return *reinterpret_cast<unsigned*>(&h);
}

// ---------- fused convert + scatter: adjf[dst*64 + pos] = src (2 edges/thread) ----------
__global__ void convert_scatter_kernel(const int* __restrict__ ei32) {
    __shared__ int s_e;
    if (threadIdx.x == 0) s_e = 0;
    __syncthreads();
    if (threadIdx.x < 64) {
        long long ie = (long long)threadIdx.x * 12345 + 7;   // < N_EDGES
        if (ei32[2 * ie + 1] != 0) atomicOr(&s_e, 1);
    }
    __syncthreads();
    int e64 = s_e ? 0 : 1;

    int gid = blockIdx.x * blockDim.x + threadIdx.x;   // edge-pair index
    if (gid >= N_EDGES / 2) return;
    int s0, s1, d0, d1;
    if (e64) {
        uint4 sv = ((const uint4*)ei32)[gid];                  // edges 2g,2g+1 src (int64)
        uint4 dv = ((const uint4*)ei32)[N_EDGES / 2 + gid];    // dst
        s0 = (int)sv.x; s1 = (int)sv.z;
        d0 = (int)dv.x; d1 = (int)dv.z;
    } else {
        int2 sv = ((const int2*)ei32)[gid];
        int2 dv = ((const int2*)ei32)[N_EDGES / 2 + gid];
        s0 = sv.x; s1 = sv.y;
        d0 = dv.x; d1 = dv.y;
    }
    int p0 = atomicAdd(&g_degi[d0], 1);
    int p1 = atomicAdd(&g_degi[d1], 1);
    if (p0 < DMAX) g_adjf[(size_t)d0 * DMAX + p0] = s0;
    if (p1 < DMAX) g_adjf[(size_t)d1 * DMAX + p1] = s1;
}

// ---------- slim per-node pass: dinv only ----------
__global__ void dinv_kernel() {
    int idx = blockIdx.x * 256 + threadIdx.x;
    if (idx < N_NODES)
        g_dinv[idx] = rsqrtf((float)(g_degi[idx] + 1));   // +1 self loop
}

// ---------------- tensor-core GEMM: C = [dinv *] A[M,128] @ W, fp16 out ----------------
// W is fp32 [128][N] row-major; converted/transposed into smem here (no prep kernel).
template <int N, int WC, bool A_HALF, bool SCALE>
__global__ void mma_gemm_kernel(const void* __restrict__ Ain,
                                const float* __restrict__ Wf,
                                __half* __restrict__ C, int M) {
    constexpr int NT  = WC / 8;
    constexpr int STR = 136;
    extern __shared__ __half sh[];
    __half* Asm = sh;              // 64 x STR
    __half* Bsm = sh + 64 * STR;   // N x STR  (Bsm[n*STR+k] = half(W[k][n]))

    int tid  = threadIdx.x;
    int row0 = blockIdx.x * 64;

    // fill B: transpose + fp32->fp16, k-pairs
    #pragma unroll
    for (int idx = tid; idx < N * 64; idx += 256) {
        int k2 = idx / N;          // 0..63 (pair of k)
        int n  = idx % N;
        float w0 = Wf[(2 * k2) * N + n];
        float w1 = Wf[(2 * k2 + 1) * N + n];
        *(__half2*)(Bsm + n * STR + 2 * k2) = __floats2half2_rn(w0, w1);
    }
    if (A_HALF) {
        const uint2* A2 = (const uint2*)Ain;
        #pragma unroll
        for (int idx = tid; idx < 64 * 32; idx += 256) {
            int r = idx >> 5, c4 = idx & 31;
            int row = row0 + r;
            uint2 v = make_uint2(0u, 0u);
            if (row < M) v = A2[(size_t)row * 32 + c4];
            *(uint2*)(Asm + r * STR + c4 * 4) = v;
        }
    } else {
        const float4* A4 = (const float4*)Ain;
        #pragma unroll
        for (int idx = tid; idx < 64 * 32; idx += 256) {
            int r = idx >> 5, c4 = idx & 31;
            int row = row0 + r;
            float4 v = make_float4(0.f, 0.f, 0.f, 0.f);
            if (row < M) v = A4[(size_t)row * 32 + c4];
            uint2 o;
            o.x = h2bits(__floats2half2_rn(v.x, v.y));
            o.y = h2bits(__floats2half2_rn(v.z, v.w));
            *(uint2*)(Asm + r * STR + c4 * 4) = o;
        }
    }
    __syncthreads();

    int lane = tid & 31, warp = tid >> 5;
    int wr = warp >> 1, wc = warp & 1;
    int gid = lane >> 2, q = lane & 3;

    float c[NT][4];
    #pragma unroll
    for (int j = 0; j < NT; j++) {
        c[j][0] = 0.f; c[j][1] = 0.f; c[j][2] = 0.f; c[j][3] = 0.f;
    }

    const __half* Abase = Asm + (wr * 16 + gid) * STR;
    #pragma unroll
    for (int s = 0; s < 8; s++) {
        int k0 = s * 16 + q * 2;
        unsigned a0 = *(const unsigned*)(Abase + k0);
        unsigned a1 = *(const unsigned*)(Abase + 8 * STR + k0);
        unsigned a2 = *(const unsigned*)(Abase + k0 + 8);
        unsigned a3 = *(const unsigned*)(Abase + 8 * STR + k0 + 8);
        #pragma unroll
        for (int j = 0; j < NT; j++) {
            const __half* Bp = Bsm + (wc * WC + j * 8 + gid) * STR + k0;
            unsigned b0 = *(const unsigned*)(Bp);
            unsigned b1 = *(const unsigned*)(Bp + 8);
            asm volatile(
                "mma.sync.aligned.m16n8k16.row.col.f32.f16.f16.f32 "
                "{%0,%1,%2,%3}, {%4,%5,%6,%7}, {%8,%9}, {%0,%1,%2,%3};"
                : "+f"(c[j][0]), "+f"(c[j][1]), "+f"(c[j][2]), "+f"(c[j][3])
                : "r"(a0), "r"(a1), "r"(a2), "r"(a3), "r"(b0), "r"(b1));
        }
    }

    int ra = row0 + wr * 16 + gid;
    int rb = ra + 8;
    float dva = 1.f, dvb = 1.f;
    if (SCALE) {
        if (ra < M) dva = g_dinv[ra];
        if (rb < M) dvb = g_dinv[rb];
    }
    #pragma unroll
    for (int j = 0; j < NT; j++) {
        int n = wc * WC + j * 8 + q * 2;
        if (ra < M)
            *(__half2*)(C + (size_t)ra * N + n) =
                __floats2half2_rn(c[j][0] * dva, c[j][1] * dva);
        if (rb < M)
            *(__half2*)(C + (size_t)rb * N + n) =
                __floats2half2_rn(c[j][2] * dvb, c[j][3] * dvb);
    }
}

// ---------- layer1 gather + relu ----------
__global__ void gather128_kernel(const __half* __restrict__ h,
                                 const float* __restrict__ bias,
                                 __half* __restrict__ agg) {
    int gtid = blockIdx.x * blockDim.x + threadIdx.x;
    int v    = gtid >> 5;
    int lane = threadIdx.x & 31;
    if (v >= N_NODES) return;
    int d = 0; float dv = 0.f;
    if (lane == 0) {
        d  = g_degi[v];
        dv = g_dinv[v];
    }
    d  = __shfl_sync(0xffffffffu, d, 0);
    dv = __shfl_sync(0xffffffffu, dv, 0);
    d  = (d < DMAX) ? d : DMAX;
    const int* adj = g_adjf + (size_t)v * DMAX;

    const uint2* h2 = (const uint2*)h;
    float4 s = h4_to_f4(h2[(size_t)v * 32 + lane]);
    float4 acc = make_float4(s.x * dv, s.y * dv, s.z * dv, s.w * dv);
    int i = 0;
    for (; i + 4 <= d; i += 4) {
        int u0 = adj[i],     u1 = adj[i + 1];
        int u2 = adj[i + 2], u3 = adj[i + 3];
        float d0 = g_dinv[u0], d1 = g_dinv[u1];
        float d2 = g_dinv[u2], d3 = g_dinv[u3];
        float4 a = h4_to_f4(h2[(size_t)u0 * 32 + lane]);
        float4 b = h4_to_f4(h2[(size_t)u1 * 32 + lane]);
        float4 cc = h4_to_f4(h2[(size_t)u2 * 32 + lane]);
        float4 dd = h4_to_f4(h2[(size_t)u3 * 32 + lane]);
        acc.x += (a.x * d0 + b.x * d1) + (cc.x * d2 + dd.x * d3);
        acc.y += (a.y * d0 + b.y * d1) + (cc.y * d2 + dd.y * d3);
        acc.z += (a.z * d0 + b.z * d1) + (cc.z * d2 + dd.z * d3);
        acc.w += (a.w * d0 + b.w * d1) + (cc.w * d2 + dd.w * d3);
    }
    for (; i < d; i++) {
        int u = adj[i];
        float du = g_dinv[u];
        float4 a = h4_to_f4(h2[(size_t)u * 32 + lane]);
        acc.x += a.x * du; acc.y += a.y * du;
        acc.z += a.z * du; acc.w += a.w * du;
    }
    float4 bb = ((const float4*)bias)[lane];
    float ox = fmaxf(bb.x + dv * acc.x, 0.f);
    float oy = fmaxf(bb.y + dv * acc.y, 0.f);
    float oz = fmaxf(bb.z + dv * acc.z, 0.f);
    float ow = fmaxf(bb.w + dv * acc.w, 0.f);
    uint2 st;
    st.x = h2bits(__floats2half2_rn(ox, oy));
    st.y = h2bits(__floats2half2_rn(oz, ow));
    ((uint2*)agg)[(size_t)v * 32 + lane] = st;
}

__device__ __forceinline__ void red_add_v4(float* p, float4 v) {
    asm volatile("red.global.add.v4.f32 [%0], {%1,%2,%3,%4};"
                 :: "l"(p), "f"(v.x), "f"(v.y), "f"(v.z), "f"(v.w)
                 : "memory");
}

// ---------------- layer2 gather + pool (+ batch/boundary + degi re-zero) ----------------
__global__ void gather64_pool_kernel(const __half* __restrict__ hs,
                                     const float* __restrict__ bias,
                                     const int* __restrict__ b32) {
    __shared__ int s_b;
    if (threadIdx.x == 0) s_b = 0;
    __syncthreads();
    if (threadIdx.x < 64) {
        long long ib = N_NODES / 2 - 1 - threadIdx.x;
        if (b32[2 * ib + 1] != 0) atomicOr(&s_b, 1);   // int32 -> nonzero whp
    }
    __syncthreads();
    int b64 = s_b ? 0 : 1;

    int gtid = blockIdx.x * blockDim.x + threadIdx.x;
    int v    = gtid >> 4;
    int sub  = threadIdx.x & 15;
    if (v >= N_NODES) return;
    int d = 0, g = 0; float dv = 0.f;
    if (sub == 0) {
        d  = g_degi[v];
        g_degi[v] = 0;                          // restore zero-invariant
        dv = g_dinv[v];
        // batch convert + sorted-boundary table (batch is sorted)
        int bc = b64 ? b32[2 * (size_t)v] : b32[v];
        int bp = -1;
        if (v > 0) bp = b64 ? b32[2 * (size_t)(v - 1)] : b32[v - 1];
        for (int gg = bp + 1; gg <= bc; gg++) g_start[gg] = v;
        if (v == N_NODES - 1)
            for (int gg = bc + 1; gg <= NUM_GRAPHS; gg++) g_start[gg] = N_NODES;
        g = bc;
    }
    d  = __shfl_sync(0xffffffffu, d, 0, 16);
    dv = __shfl_sync(0xffffffffu, dv, 0, 16);
    g  = __shfl_sync(0xffffffffu, g, 0, 16);
    d  = (d < DMAX) ? d : DMAX;
    const int* adj = g_adjf + (size_t)v * DMAX;

    const uint2* hs2p = (const uint2*)hs;
    float4 acc = h4_to_f4(hs2p[(size_t)v * 16 + sub]);
    int i = 0;
    for (; i + 4 <= d; i += 4) {
        int u0 = adj[i],     u1 = adj[i + 1];
        int u2 = adj[i + 2], u3 = adj[i + 3];
        float4 a = h4_to_f4(hs2p[(size_t)u0 * 16 + sub]);
        float4 b = h4_to_f4(hs2p[(size_t)u1 * 16 + sub]);
        float4 c = h4_to_f4(hs2p[(size_t)u2 * 16 + sub]);
        float4 dd = h4_to_f4(hs2p[(size_t)u3 * 16 + sub]);
        acc.x += (a.x + b.x) + (c.x + dd.x);
        acc.y += (a.y + b.y) + (c.y + dd.y);
        acc.z += (a.z + b.z) + (c.z + dd.z);
        acc.w += (a.w + b.w) + (c.w + dd.w);
    }
    for (; i < d; i++) {
        int u = adj[i];
        float4 a = h4_to_f4(hs2p[(size_t)u * 16 + sub]);
        acc.x += a.x; acc.y += a.y; acc.z += a.z; acc.w += a.w;
    }
    float4 bb = ((const float4*)bias)[sub];
    float4 o = make_float4(bb.x + dv * acc.x, bb.y + dv * acc.y,
                           bb.z + dv * acc.z, bb.w + dv * acc.w);
    red_add_v4(g_pool + (size_t)g * 64 + sub * 4, o);
}

// ---------------- final: out = (pool / max(cnt,1)) @ Wl + bl; restore zeros ----------------
__global__ void final_kernel(const float* __restrict__ Wl,
                             const float* __restrict__ bl,
                             float* __restrict__ out) {
    int g = blockIdx.x;
    int n = threadIdx.x;
    __shared__ float ps[64];
    float cnt = (float)(g_start[g + 1] - g_start[g]);
    float inv = 1.0f / fmaxf(cnt, 1.0f);
    ps[n] = g_pool[g * 64 + n] * inv;
    g_pool[g * 64 + n] = 0.0f;          // restore zero-invariant
    __syncthreads();
    float acc = bl[n];
    #pragma unroll
    for (int k = 0; k < 64; k++) acc += ps[k] * Wl[k * 64 + n];
    out[g * 64 + n] = acc;
}

// ---------------- launch ----------------
extern "C" void kernel_launch(void* const* d_in, const int* in_sizes, int n_in,
                              void* d_out, int out_size) {
    const float* x    = (const float*)d_in[0];
    const int*   ei32 = (const int*)d_in[1];
    const int*   b32  = (const int*)d_in[2];
    const float* W1   = (const float*)d_in[3];
    const float* b1   = (const float*)d_in[4];
    const float* W2   = (const float*)d_in[5];
    const float* b2   = (const float*)d_in[6];
    const float* Wl   = (const float*)d_in[7];
    const float* bl   = (const float*)d_in[8];
    float* out = (float*)d_out;

    __half *p_h1, *p_agg1, *p_hs2;
    cudaGetSymbolAddress((void**)&p_h1,   g_h1);
    cudaGetSymbolAddress((void**)&p_agg1, g_agg1);
    cudaGetSymbolAddress((void**)&p_hs2,  g_hs2);

    const int SMEM1 = (64 + 128) * 136 * 2;   // 52224
    const int SMEM2 = (64 + 64) * 136 * 2;    // 34816
    cudaFuncSetAttribute((const void*)mma_gemm_kernel<128, 64, false, false>,
                         cudaFuncAttributeMaxDynamicSharedMemorySize, SMEM1);
    cudaFuncSetAttribute((const void*)mma_gemm_kernel<64, 32, true, true>,
                         cudaFuncAttributeMaxDynamicSharedMemorySize, SMEM2);

    const int GRID_M = (N_NODES + 63) / 64;   // 782

    // ---- fork: side stream = GEMM1 (converts W1 in-kernel) -> [ev_h1] ----
    cudaEventRecord(s_ev_fork, 0);
    cudaStreamWaitEvent(s_side, s_ev_fork, 0);
    mma_gemm_kernel<128, 64, false, false>
        <<<GRID_M, 256, SMEM1, s_side>>>(x, W1, p_h1, N_NODES);
    cudaEventRecord(s_ev_h1, s_side);

    // ---- main stream: fused adjacency build + dinv ----
    convert_scatter_kernel<<<(N_EDGES / 2 + 255) / 256, 256>>>(ei32);
    dinv_kernel<<<NBLK, 256>>>();

    // ---- join: gather128 needs adjacency/dinv + h1 ----
    cudaStreamWaitEvent(0, s_ev_h1, 0);
    gather128_kernel<<<(N_NODES * 32 + 255) / 256, 256>>>(p_h1, b1, p_agg1);

    // layer 2 (+ fused pool/batch/boundaries/degi-zero)
    mma_gemm_kernel<64, 32, true, true>
        <<<GRID_M, 256, SMEM2>>>(p_agg1, W2, p_hs2, N_NODES);
    gather64_pool_kernel<<<(N_NODES * 16 + 255) / 256, 256>>>(p_hs2, b2, b32);

    // final linear (cnt from sorted-batch boundaries; restores g_pool zeros)
    final_kernel<<<NUM_GRAPHS, 64>>>(Wl, bl, out);
}

// round 13
// speedup vs baseline: 1.3989x; 1.3989x over previous
#include <cuda_runtime.h>
#include <cuda_fp16.h>

#define N_NODES   50000
#define N_EDGES   800000
#define NUM_GRAPHS 512
#define F1 128
#define F2 64
#define DMAX 64    // fixed adjacency stride; P(deg>=64) ~ 1e-19 per node
#define NBLK 196   // ceil(N_NODES/256)

typedef unsigned long long u64;

// ---------------- scratch (device globals: allocation-free) ----------------
// INVARIANT at kernel_launch entry: g_degi == 0, g_pool == 0 (zero-init at
// load; node_kernel re-zeroes g_degi, final_kernel re-zeroes g_pool each run).
__device__ int    g_degi[N_NODES];
__device__ int    g_deg[N_NODES];                // clamped degree (consumer copy)
__device__ int    g_adjf[(size_t)N_NODES * DMAX];// fixed-stride adjacency (src per dst)
__device__ int    g_start[NUM_GRAPHS + 1];       // first node index of graph g
__device__ float  g_dinv[N_NODES];
__device__ __half g_w1t[128 * 128];              // W1^T fp16 [n][k]
__device__ __half g_w2t[64 * 128];               // W2^T fp16 [n][k]
__device__ __half g_h1[(size_t)N_NODES * F1];    // x@W1 (fp16)
__device__ __half g_agg1[(size_t)N_NODES * F1];  // relu(gcn1) (fp16)
__device__ __half g_hs2[(size_t)N_NODES * F2];   // dinv * (relu(agg1)@W2) (fp16)
__device__ float  g_pool[NUM_GRAPHS * F2];
__device__ int    g_batch[N_NODES];

// ---------------- static side stream + events ----------------
static cudaStream_t s_side;
static cudaEvent_t  s_ev_fork, s_ev_h1;
namespace {
struct StreamInit {
    StreamInit() {
        cudaStreamCreateWithFlags(&s_side, cudaStreamNonBlocking);
        cudaEventCreateWithFlags(&s_ev_fork, cudaEventDisableTiming);
        cudaEventCreateWithFlags(&s_ev_h1,   cudaEventDisableTiming);
    }
};
static StreamInit s_stream_init;
}

// ---------------- helpers ----------------
__device__ __forceinline__ unsigned h2bits(__half2 h) {
    return *reinterpret_cast<unsigned*>(&h);
}
__device__ __forceinline__ u64 pack2(float x) {
    u64 r; asm("mov.b64 %0, {%1, %1};" : "=l"(r) : "f"(x)); return r;
}
__device__ __forceinline__ void ffma2(u64& d, u64 a, u64 b) {
    asm("fma.rn.f32x2 %0, %1, %2, %0;" : "+l"(d) : "l"(a), "l"(b));
}
__device__ __forceinline__ void add2(u64& d, u64 a) {
    asm("add.rn.f32x2 %0, %0, %1;" : "+l"(d) : "l"(a));
}
__device__ __forceinline__ float2 unpack2(u64 v) {
    float2 r; asm("mov.b64 {%0, %1}, %2;" : "=f"(r.x), "=f"(r.y) : "l"(v)); return r;
}
// uint2 (4 halves) -> two packed f32x2 values
__device__ __forceinline__ void h4_to_2xf32x2(uint2 w, u64& lo, u64& hi) {
    float2 a = __half22float2(*reinterpret_cast<__half2*>(&w.x));
    float2 b = __half22float2(*reinterpret_cast<__half2*>(&w.y));
    lo = *reinterpret_cast<u64*>(&a);
    hi = *reinterpret_cast<u64*>(&b);
}

// ---------------- prep: transpose + fp16-convert weights (side, once) ----------------
__global__ void prep_w_kernel(const float* __restrict__ W1,
                              const float* __restrict__ W2) {
    int i = blockIdx.x * 256 + threadIdx.x;
    if (i < 128 * 128) {
        int n = i >> 7, k = i & 127;
        g_w1t[i] = __float2half(W1[k * 128 + n]);
    }
    if (i < 64 * 128) {
        int n = i >> 7, k = i & 127;
        g_w2t[i] = __float2half(W2[k * 64 + n]);
    }
}

// ---------- fused convert + scatter: adjf[dst*64 + pos] = src (2 edges/thread) ----------
__global__ void convert_scatter_kernel(const int* __restrict__ ei32) {
    __shared__ int s_e;
    if (threadIdx.x == 0) s_e = 0;
    __syncthreads();
    if (threadIdx.x < 64) {
        long long ie = (long long)threadIdx.x * 12345 + 7;   // < N_EDGES
        if (ei32[2 * ie + 1] != 0) atomicOr(&s_e, 1);
    }
    __syncthreads();
    int e64 = s_e ? 0 : 1;

    int gid = blockIdx.x * blockDim.x + threadIdx.x;   // edge-pair index
    if (gid >= N_EDGES / 2) return;
    int s0, s1, d0, d1;
    if (e64) {
        uint4 sv = ((const uint4*)ei32)[gid];                  // edges 2g,2g+1 src (int64)
        uint4 dv = ((const uint4*)ei32)[N_EDGES / 2 + gid];    // dst
        s0 = (int)sv.x; s1 = (int)sv.z;
        d0 = (int)dv.x; d1 = (int)dv.z;
    } else {
        int2 sv = ((const int2*)ei32)[gid];
        int2 dv = ((const int2*)ei32)[N_EDGES / 2 + gid];
        s0 = sv.x; s1 = sv.y;
        d0 = dv.x; d1 = dv.y;
    }
    int p0 = atomicAdd(&g_degi[d0], 1);
    int p1 = atomicAdd(&g_degi[d1], 1);
    if (p0 < DMAX) g_adjf[(size_t)d0 * DMAX + p0] = s0;
    if (p1 < DMAX) g_adjf[(size_t)d1 * DMAX + p1] = s1;
}

// ---------- per-node pass: deg/dinv, re-zero degi, batch boundaries ----------
__global__ void node_kernel(const int* __restrict__ b32) {
    __shared__ int s_b;
    if (threadIdx.x == 0) s_b = 0;
    __syncthreads();
    if (threadIdx.x < 64) {
        long long ib = N_NODES / 2 - 1 - threadIdx.x;
        if (b32[2 * ib + 1] != 0) atomicOr(&s_b, 1);   // int32 -> nonzero whp
    }
    __syncthreads();
    int b64 = s_b ? 0 : 1;

    int idx = blockIdx.x * 256 + threadIdx.x;
    if (idx >= N_NODES) return;
    int d = g_degi[idx];
    g_degi[idx] = 0;                       // restore zero-invariant
    g_deg[idx]  = (d < DMAX) ? d : DMAX;
    g_dinv[idx] = rsqrtf((float)(d + 1));  // +1 self loop

    // batch convert + sorted-boundary table
    int bc = b64 ? b32[2 * (size_t)idx] : b32[idx];
    g_batch[idx] = bc;
    int bp = -1;
    if (idx > 0) bp = b64 ? b32[2 * (size_t)(idx - 1)] : b32[idx - 1];
    for (int g = bp + 1; g <= bc; g++) g_start[g] = idx;
    if (idx == N_NODES - 1)
        for (int g = bc + 1; g <= NUM_GRAPHS; g++) g_start[g] = N_NODES;
}

// ---------------- tensor-core GEMM: C = [dinv *] A[M,128] @ Wt^T, fp16 out ----------------
template <int N, int WC, bool A_HALF, bool SCALE>
__global__ void mma_gemm_kernel(const void* __restrict__ Ain,
                                const __half* __restrict__ Wt,
                                __half* __restrict__ C, int M) {
    constexpr int NT  = WC / 8;
    constexpr int STR = 136;
    extern __shared__ __half sh[];
    __half* Asm = sh;              // 64 x STR
    __half* Bsm = sh + 64 * STR;   // N x STR

    int tid  = threadIdx.x;
    int row0 = blockIdx.x * 64;

    const uint4* Wt4 = (const uint4*)Wt;
    #pragma unroll
    for (int idx = tid; idx < N * 16; idx += 256) {
        int n = idx >> 4, kc = idx & 15;
        *(uint4*)(Bsm + n * STR + kc * 8) = Wt4[idx];
    }
    if (A_HALF) {
        const uint2* A2 = (const uint2*)Ain;
        #pragma unroll
        for (int idx = tid; idx < 64 * 32; idx += 256) {
            int r = idx >> 5, c4 = idx & 31;
            int row = row0 + r;
            uint2 v = make_uint2(0u, 0u);
            if (row < M) v = A2[(size_t)row * 32 + c4];
            *(uint2*)(Asm + r * STR + c4 * 4) = v;
        }
    } else {
        const float4* A4 = (const float4*)Ain;
        #pragma unroll
        for (int idx = tid; idx < 64 * 32; idx += 256) {
            int r = idx >> 5, c4 = idx & 31;
            int row = row0 + r;
            float4 v = make_float4(0.f, 0.f, 0.f, 0.f);
            if (row < M) v = A4[(size_t)row * 32 + c4];
            uint2 o;
            o.x = h2bits(__floats2half2_rn(v.x, v.y));
            o.y = h2bits(__floats2half2_rn(v.z, v.w));
            *(uint2*)(Asm + r * STR + c4 * 4) = o;
        }
    }
    __syncthreads();

    int lane = tid & 31, warp = tid >> 5;
    int wr = warp >> 1, wc = warp & 1;
    int gid = lane >> 2, q = lane & 3;

    float c[NT][4];
    #pragma unroll
    for (int j = 0; j < NT; j++) {
        c[j][0] = 0.f; c[j][1] = 0.f; c[j][2] = 0.f; c[j][3] = 0.f;
    }

    const __half* Abase = Asm + (wr * 16 + gid) * STR;
    #pragma unroll
    for (int s = 0; s < 8; s++) {
        int k0 = s * 16 + q * 2;
        unsigned a0 = *(const unsigned*)(Abase + k0);
        unsigned a1 = *(const unsigned*)(Abase + 8 * STR + k0);
        unsigned a2 = *(const unsigned*)(Abase + k0 + 8);
        unsigned a3 = *(const unsigned*)(Abase + 8 * STR + k0 + 8);
        #pragma unroll
        for (int j = 0; j < NT; j++) {
            const __half* Bp = Bsm + (wc * WC + j * 8 + gid) * STR + k0;
            unsigned b0 = *(const unsigned*)(Bp);
            unsigned b1 = *(const unsigned*)(Bp + 8);
            asm volatile(
                "mma.sync.aligned.m16n8k16.row.col.f32.f16.f16.f32 "
                "{%0,%1,%2,%3}, {%4,%5,%6,%7}, {%8,%9}, {%0,%1,%2,%3};"
                : "+f"(c[j][0]), "+f"(c[j][1]), "+f"(c[j][2]), "+f"(c[j][3])
                : "r"(a0), "r"(a1), "r"(a2), "r"(a3), "r"(b0), "r"(b1));
        }
    }

    int ra = row0 + wr * 16 + gid;
    int rb = ra + 8;
    float dva = 1.f, dvb = 1.f;
    if (SCALE) {
        if (ra < M) dva = g_dinv[ra];
        if (rb < M) dvb = g_dinv[rb];
    }
    #pragma unroll
    for (int j = 0; j < NT; j++) {
        int n = wc * WC + j * 8 + q * 2;
        if (ra < M)
            *(__half2*)(C + (size_t)ra * N + n) =
                __floats2half2_rn(c[j][0] * dva, c[j][1] * dva);
        if (rb < M)
            *(__half2*)(C + (size_t)rb * N + n) =
                __floats2half2_rn(c[j][2] * dvb, c[j][3] * dvb);
    }
}

// ---------- layer1 gather + relu (f32x2 accumulation, 32-bit indexing) ----------
__global__ void gather128_kernel(const __half* __restrict__ h,
                                 const float* __restrict__ bias,
                                 __half* __restrict__ agg) {
    int gtid = blockIdx.x * blockDim.x + threadIdx.x;
    int v    = gtid >> 5;
    int lane = threadIdx.x & 31;
    if (v >= N_NODES) return;
    int d = 0; float dv = 0.f;
    if (lane == 0) {
        d  = g_deg[v];
        dv = g_dinv[v];
    }
    d  = __shfl_sync(0xffffffffu, d, 0);
    dv = __shfl_sync(0xffffffffu, dv, 0);
    const int* adj = g_adjf + (unsigned)v * DMAX;

    const uint2* h2 = (const uint2*)h;
    u64 acc0 = 0ull, acc1 = 0ull;
    {
        u64 s0, s1;
        h4_to_2xf32x2(h2[(unsigned)v * 32 + lane], s0, s1);
        u64 dvp = pack2(dv);
        ffma2(acc0, s0, dvp);
        ffma2(acc1, s1, dvp);
    }
    int i = 0;
    for (; i + 4 <= d; i += 4) {
        int u0 = adj[i],     u1 = adj[i + 1];
        int u2 = adj[i + 2], u3 = adj[i + 3];
        u64 p0 = pack2(g_dinv[u0]), p1 = pack2(g_dinv[u1]);
        u64 p2 = pack2(g_dinv[u2]), p3 = pack2(g_dinv[u3]);
        u64 a0, a1, b0, b1, c0, c1, e0, e1;
        h4_to_2xf32x2(h2[(unsigned)u0 * 32 + lane], a0, a1);
        h4_to_2xf32x2(h2[(unsigned)u1 * 32 + lane], b0, b1);
        h4_to_2xf32x2(h2[(unsigned)u2 * 32 + lane], c0, c1);
        h4_to_2xf32x2(h2[(unsigned)u3 * 32 + lane], e0, e1);
        ffma2(acc0, a0, p0); ffma2(acc1, a1, p0);
        ffma2(acc0, b0, p1); ffma2(acc1, b1, p1);
        ffma2(acc0, c0, p2); ffma2(acc1, c1, p2);
        ffma2(acc0, e0, p3); ffma2(acc1, e1, p3);
    }
    for (; i < d; i++) {
        int u = adj[i];
        u64 p = pack2(g_dinv[u]);
        u64 a0, a1;
        h4_to_2xf32x2(h2[(unsigned)u * 32 + lane], a0, a1);
        ffma2(acc0, a0, p);
        ffma2(acc1, a1, p);
    }
    float2 f0 = unpack2(acc0);
    float2 f1 = unpack2(acc1);
    float4 bb = ((const float4*)bias)[lane];
    float ox = fmaxf(bb.x + dv * f0.x, 0.f);
    float oy = fmaxf(bb.y + dv * f0.y, 0.f);
    float oz = fmaxf(bb.z + dv * f1.x, 0.f);
    float ow = fmaxf(bb.w + dv * f1.y, 0.f);
    uint2 st;
    st.x = h2bits(__floats2half2_rn(ox, oy));
    st.y = h2bits(__floats2half2_rn(oz, ow));
    ((uint2*)agg)[(unsigned)v * 32 + lane] = st;
}

__device__ __forceinline__ void red_add_v4(float* p, float4 v) {
    asm volatile("red.global.add.v4.f32 [%0], {%1,%2,%3,%4};"
                 :: "l"(p), "f"(v.x), "f"(v.y), "f"(v.z), "f"(v.w)
                 : "memory");
}

// ---------------- layer2 gather + pool (f32x2 accumulation) ----------------
__global__ void gather64_pool_kernel(const __half* __restrict__ hs,
                                     const float* __restrict__ bias) {
    int gtid = blockIdx.x * blockDim.x + threadIdx.x;
    int v    = gtid >> 4;
    int sub  = threadIdx.x & 15;
    if (v >= N_NODES) return;
    int d = 0, g = 0; float dv = 0.f;
    if (sub == 0) {
        d  = g_deg[v];
        dv = g_dinv[v];
        g  = g_batch[v];
    }
    d  = __shfl_sync(0xffffffffu, d, 0, 16);
    dv = __shfl_sync(0xffffffffu, dv, 0, 16);
    g  = __shfl_sync(0xffffffffu, g, 0, 16);
    const int* adj = g_adjf + (unsigned)v * DMAX;

    const uint2* hs2p = (const uint2*)hs;
    u64 acc0, acc1;
    h4_to_2xf32x2(hs2p[(unsigned)v * 16 + sub], acc0, acc1);   // self loop
    int i = 0;
    for (; i + 4 <= d; i += 4) {
        int u0 = adj[i],     u1 = adj[i + 1];
        int u2 = adj[i + 2], u3 = adj[i + 3];
        u64 a0, a1, b0, b1, c0, c1, e0, e1;
        h4_to_2xf32x2(hs2p[(unsigned)u0 * 16 + sub], a0, a1);
        h4_to_2xf32x2(hs2p[(unsigned)u1 * 16 + sub], b0, b1);
        h4_to_2xf32x2(hs2p[(unsigned)u2 * 16 + sub], c0, c1);
        h4_to_2xf32x2(hs2p[(unsigned)u3 * 16 + sub], e0, e1);
        add2(acc0, a0); add2(acc1, a1);
        add2(acc0, b0); add2(acc1, b1);
        add2(acc0, c0); add2(acc1, c1);
        add2(acc0, e0); add2(acc1, e1);
    }
    for (; i < d; i++) {
        int u = adj[i];
        u64 a0, a1;
        h4_to_2xf32x2(hs2p[(unsigned)u * 16 + sub], a0, a1);
        add2(acc0, a0);
        add2(acc1, a1);
    }
    float2 f0 = unpack2(acc0);
    float2 f1 = unpack2(acc1);
    float4 bb = ((const float4*)bias)[sub];
    float4 o = make_float4(bb.x + dv * f0.x, bb.y + dv * f0.y,
                           bb.z + dv * f1.x, bb.w + dv * f1.y);
    red_add_v4(g_pool + (size_t)g * 64 + sub * 4, o);
}

// ---------------- final: out = (pool / max(cnt,1)) @ Wl + bl; restore zeros ----------------
__global__ void final_kernel(const float* __restrict__ Wl,
                             const float* __restrict__ bl,
                             float* __restrict__ out) {
    int g = blockIdx.x;
    int n = threadIdx.x;
    __shared__ float ps[64];
    float cnt = (float)(g_start[g + 1] - g_start[g]);
    float inv = 1.0f / fmaxf(cnt, 1.0f);
    ps[n] = g_pool[g * 64 + n] * inv;
    g_pool[g * 64 + n] = 0.0f;          // restore zero-invariant
    __syncthreads();
    float acc = bl[n];
    #pragma unroll
    for (int k = 0; k < 64; k++) acc += ps[k] * Wl[k * 64 + n];
    out[g * 64 + n] = acc;
}

// ---------------- launch ----------------
extern "C" void kernel_launch(void* const* d_in, const int* in_sizes, int n_in,
                              void* d_out, int out_size) {
    const float* x    = (const float*)d_in[0];
    const int*   ei32 = (const int*)d_in[1];
    const int*   b32  = (const int*)d_in[2];
    const float* W1   = (const float*)d_in[3];
    const float* b1   = (const float*)d_in[4];
    const float* W2   = (const float*)d_in[5];
    const float* b2   = (const float*)d_in[6];
    const float* Wl   = (const float*)d_in[7];
    const float* bl   = (const float*)d_in[8];
    float* out = (float*)d_out;

    __half *p_h1, *p_agg1, *p_hs2, *p_w1t, *p_w2t;
    cudaGetSymbolAddress((void**)&p_h1,   g_h1);
    cudaGetSymbolAddress((void**)&p_agg1, g_agg1);
    cudaGetSymbolAddress((void**)&p_hs2,  g_hs2);
    cudaGetSymbolAddress((void**)&p_w1t,  g_w1t);
    cudaGetSymbolAddress((void**)&p_w2t,  g_w2t);

    const int SMEM1 = (64 + 128) * 136 * 2;   // 52224
    const int SMEM2 = (64 + 64) * 136 * 2;    // 34816
    cudaFuncSetAttribute((const void*)mma_gemm_kernel<128, 64, false, false>,
                         cudaFuncAttributeMaxDynamicSharedMemorySize, SMEM1);
    cudaFuncSetAttribute((const void*)mma_gemm_kernel<64, 32, true, true>,
                         cudaFuncAttributeMaxDynamicSharedMemorySize, SMEM2);

    const int GRID_M = (N_NODES + 63) / 64;   // 782

    // ---- fork: side stream = prep_w -> GEMM1 -> [ev_h1] ----
    cudaEventRecord(s_ev_fork, 0);
    cudaStreamWaitEvent(s_side, s_ev_fork, 0);
    prep_w_kernel<<<64, 256, 0, s_side>>>(W1, W2);
    mma_gemm_kernel<128, 64, false, false>
        <<<GRID_M, 256, SMEM1, s_side>>>(x, p_w1t, p_h1, N_NODES);
    cudaEventRecord(s_ev_h1, s_side);

    // ---- main stream: fused adjacency build ----
    convert_scatter_kernel<<<(N_EDGES / 2 + 255) / 256, 256>>>(ei32);
    node_kernel<<<NBLK, 256>>>(b32);

    // ---- join: gather128 needs adjacency + h1 ----
    cudaStreamWaitEvent(0, s_ev_h1, 0);
    gather128_kernel<<<(N_NODES * 32 + 255) / 256, 256>>>(p_h1, b1, p_agg1);

    // layer 2 (+ fused pool)
    mma_gemm_kernel<64, 32, true, true>
        <<<GRID_M, 256, SMEM2>>>(p_agg1, p_w2t, p_hs2, N_NODES);
    gather64_pool_kernel<<<(N_NODES * 16 + 255) / 256, 256>>>(p_hs2, b2);

    // final linear (cnt from sorted-batch boundaries; restores g_pool zeros)
    final_kernel<<<NUM_GRAPHS, 64>>>(Wl, bl, out);
}